// round 15
// baseline (speedup 1.0000x reference)
#include <cuda_runtime.h>
#include <cuda_fp16.h>
#include <cfloat>
#include <cstdint>

#define BB 8
#define CC 3
#define HH 1080
#define WW 1920
#define KK 256
#define NBASIS 25
#define GBINS 4096              // bins centered at g/4096, width 1/4096 (magic-RN)
#define NBINS 4097              // g in [0, 4096]
#define NBINS_PAD 4100          // pad to uint4 multiple
#define NSEG (KK + 1)           // 257 extended segments
#define PIX_PER_BATCH (CC * HH * WW)   // 6,220,800
#define NF4 (PIX_PER_BATCH / 4)        // 1,555,200
#define GX 148                          // blocks per batch: 148*8 = 1184 CTAs
#define STRIDE (GX * 256)               // 37,888
#define MAGIC 8388608.0f                // 2^23

// Bin entry (uint32), bin g covers [(2g-1)/8192, (2g+1)/8192):
//   pure bin -> lo16 = half(y at center g/4096), hi16 = half(dy across bin)
//   kinked   -> lo16 = fp16 NaN with payload 0x7C00|(k0+1), hi16 = 0x7C00
__device__ uint32_t gBinsU[BB * NBINS_PAD];
__device__ float    gSegHi[BB * NSEG];   // segment upper bound E[k] (FLT_MAX for k=K)
__device__ float2   gSegAB[BB * NSEG];   // exact (slope, intercept)

// ---------------------------------------------------------------------------
// Table builder: grid (BB, 17), 256 threads. (identical to R11 winner)
// ---------------------------------------------------------------------------
__global__ void tmo_tables(const float* __restrict__ w,
                           const float* __restrict__ E,
                           const float* __restrict__ f0,
                           const float* __restrict__ Hb) {
    __shared__ float sE[KK];
    __shared__ float sC[KK];
    const int b = blockIdx.x;
    const int part = blockIdx.y;
    const int t = threadIdx.x;

    {
        float acc = f0[t];
        #pragma unroll
        for (int n = 0; n < NBASIS; n++)
            acc = fmaf(Hb[t * NBASIS + n], w[b * NBASIS + n], acc);
        sE[t] = E[t];
        sC[t] = acc;
    }
    __syncthreads();

    if (part == 16) {
        for (int k = t; k < NSEG; k += blockDim.x) {
            float hi; float2 ab;
            if (k == 0) {
                hi = sE[0];            ab = make_float2(0.0f, sC[0]);
            } else if (k == KK) {
                hi = FLT_MAX;          ab = make_float2(0.0f, sC[KK - 1]);
            } else {
                float a = (sC[k] - sC[k - 1]) / (sE[k] - sE[k - 1]);
                hi = sE[k];            ab = make_float2(a, fmaf(-a, sE[k - 1], sC[k - 1]));
            }
            gSegHi[b * NSEG + k] = hi;
            gSegAB[b * NSEG + k] = ab;
        }
    }

    const int g = part * 256 + t;
    if (g < NBINS) {
        // RN bin boundaries (exact: odd * 2^-13)
        float left  = (float)(2 * g - 1) * (1.0f / 8192.0f);
        float right = (float)(2 * g + 1) * (1.0f / 8192.0f);
        int lo = 0, hi = KK;
        while (lo < hi) {                // k0 = #E <= left
            int mid = (lo + hi) >> 1;
            if (sE[mid] <= left) lo = mid + 1; else hi = mid;
        }
        int k0 = lo;
        float upper = (k0 < KK) ? sE[k0] : FLT_MAX;
        uint32_t u;
        if (upper >= right) {
            // entire bin inside extended segment k0: center value + per-bin delta
            float yc, dy;
            if (k0 == 0) {
                yc = sC[0];            dy = 0.0f;
            } else if (k0 == KK) {
                yc = sC[KK - 1];       dy = 0.0f;
            } else {
                float a = (sC[k0] - sC[k0 - 1]) / (sE[k0] - sE[k0 - 1]);
                float bint = fmaf(-a, sE[k0 - 1], sC[k0 - 1]);
                float xc = (float)g * (1.0f / 4096.0f);        // exact
                yc = fmaf(a, xc, bint);
                dy = a * (1.0f / 4096.0f);
            }
            uint16_t hc = __half_as_ushort(__float2half_rn(yc));
            uint16_t hd = __half_as_ushort(__float2half_rn(dy));
            u = ((uint32_t)hd << 16) | hc;          // finite halfs: never NaN-pattern
        } else {
            u = 0x7C000000u | (0x7C00u | (uint32_t)(k0 + 1));  // NaN sentinel + payload
        }
        gBinsU[b * NBINS_PAD + g] = u;
    } else if (part == 16 && g < NBINS_PAD) {
        gBinsU[b * NBINS_PAD + g] = 0;   // padding
    }
}

// ---------------------------------------------------------------------------
// Fast path runs unconditionally: magic-RN index, LDS.32, __half22float2,
// center+delta lerp. Kink detected by INTEGER NaN-pattern test on u (resolves
// right after the LDS, overlapping the FFMA chain). Slow path: two branchless
// advance steps (cover <=2 breakpoints/bin, ~99.8% of kinked lanes) + rare
// while, then exact fp32 segment evaluation.
// ---------------------------------------------------------------------------
__device__ __forceinline__ float tmo_eval(float x, const uint32_t* sBins,
                                          const float* sHi, const float2* sAB) {
    float s = fmaf(x, 4096.0f, MAGIC);          // RN -> integer g in mantissa
    int g = __float_as_int(s) & 0x1FFF;         // g in [0, 4096]
    uint32_t u = sBins[g];
    float2 f = __half22float2(*reinterpret_cast<const __half2*>(&u));  // (yc, dy)
    float gf = s - MAGIC;                       // exact (Sterbenz)
    float frac = fmaf(x, 4096.0f, -gf);         // exact, in [-0.5, 0.5]
    float y = fmaf(f.y, frac, f.x);
    if ((u & 0x7C00u) == 0x7C00u) {             // lo16 exponent all-ones => kinked
        int k = (int)(u & 0x3FFu) - 1;
        k += (x >= sHi[k]);                     // branchless advance 1
        k += (x >= sHi[k]);                     // branchless advance 2
        while (x >= sHi[k]) k++;                // pathological bins only
        float2 ab = sAB[k];
        y = fmaf(ab.x, x, ab.y);
    }
    return __saturatef(y);
}

// ---------------------------------------------------------------------------
// Main kernel: grid (148, 8) = 1184 blocks = one uniform wave at 8 CTAs/SM
// (~19.5 KB smem, 32-reg cap). Software pipeline: next LDG.128 in flight.
// ---------------------------------------------------------------------------
__global__ void __launch_bounds__(256, 8)
tmo_apply(const float* __restrict__ img, float* __restrict__ out) {
    __shared__ uint32_t sBins[NBINS_PAD];   // 16.0 KB
    __shared__ float    sHi[NSEG];          // ~1 KB
    __shared__ float2   sAB[NSEG];          // ~2 KB

    const int b = blockIdx.y;

    {
        const uint4* src = reinterpret_cast<const uint4*>(gBinsU + (size_t)b * NBINS_PAD);
        uint4* dst = reinterpret_cast<uint4*>(sBins);
        for (int i = threadIdx.x; i < NBINS_PAD / 4; i += blockDim.x) dst[i] = src[i];
        for (int i = threadIdx.x; i < NSEG; i += blockDim.x) {
            sHi[i] = gSegHi[b * NSEG + i];
            sAB[i] = gSegAB[b * NSEG + i];
        }
    }
    __syncthreads();

    const float4* in4  = reinterpret_cast<const float4*>(img + (size_t)b * PIX_PER_BATCH);
    float4*       out4 = reinterpret_cast<float4*>(out + (size_t)b * PIX_PER_BATCH);

    int i = blockIdx.x * blockDim.x + threadIdx.x;   // < STRIDE <= NF4, so >=1 elem

    float4 v = in4[i];
    int nxt = i + STRIDE;

    #pragma unroll 1
    while (nxt < NF4) {
        float4 vn = in4[nxt];            // prefetch: overlaps with processing below
        float4 r;
        r.x = tmo_eval(v.x, sBins, sHi, sAB);
        r.y = tmo_eval(v.y, sBins, sHi, sAB);
        r.z = tmo_eval(v.z, sBins, sHi, sAB);
        r.w = tmo_eval(v.w, sBins, sHi, sAB);
        out4[i] = r;
        v = vn;
        i = nxt;
        nxt += STRIDE;
    }
    {
        float4 r;
        r.x = tmo_eval(v.x, sBins, sHi, sAB);
        r.y = tmo_eval(v.y, sBins, sHi, sAB);
        r.z = tmo_eval(v.z, sBins, sHi, sAB);
        r.w = tmo_eval(v.w, sBins, sHi, sAB);
        out4[i] = r;
    }
}

extern "C" void kernel_launch(void* const* d_in, const int* in_sizes, int n_in,
                              void* d_out, int out_size) {
    const float* hdr = (const float*)d_in[0];   // [B,C,H,W]
    const float* w   = (const float*)d_in[1];   // [B,NB]
    const float* E   = (const float*)d_in[2];   // [K]
    const float* f0  = (const float*)d_in[3];   // [K]
    const float* Hb  = (const float*)d_in[4];   // [K,NB]
    float* out = (float*)d_out;

    tmo_tables<<<dim3(BB, 17), 256>>>(w, E, f0, Hb);

    dim3 grid(GX, BB);   // 1184 blocks = single uniform wave at 8 CTAs/SM
    tmo_apply<<<grid, 256>>>(hdr, out);
}

// round 16
// speedup vs baseline: 1.1258x; 1.1258x over previous
#include <cuda_runtime.h>
#include <cuda_fp16.h>
#include <cfloat>
#include <cstdint>

#define BB 8
#define CC 3
#define HH 1080
#define WW 1920
#define KK 256
#define NBASIS 25
#define GBINS 4096              // bins centered at g/4096, width 1/4096 (magic-RN)
#define NBINS 4097              // g in [0, 4096]
#define NBINS_PAD 4100          // pad to uint4 multiple
#define NSEG (KK + 1)           // 257 extended segments
#define PIX_PER_BATCH (CC * HH * WW)   // 6,220,800
#define NF4 (PIX_PER_BATCH / 4)        // 1,555,200
#define GX 148                          // blocks per batch: 148*8 = 1184 CTAs
#define STRIDE (GX * 256)               // 37,888
#define MAGIC 8388608.0f                // 2^23

// Bin entry (uint32), bin g covers [(2g-1)/8192, (2g+1)/8192):
//   pure bin -> lo16 = half(y at center g/4096), hi16 = half(dy across bin)
//   kinked   -> lo16 = fp16 NaN with payload 0x7C00|(k0+1), hi16 = 0x7C00
__device__ uint32_t gBinsU[BB * NBINS_PAD];
__device__ float    gSegHi[BB * NSEG];   // segment upper bound E[k] (FLT_MAX for k=K)
__device__ float2   gSegAB[BB * NSEG];   // exact (slope, intercept)

// ---------------------------------------------------------------------------
// Table builder: grid (BB, 17), 256 threads. (identical to R11 winner)
// ---------------------------------------------------------------------------
__global__ void tmo_tables(const float* __restrict__ w,
                           const float* __restrict__ E,
                           const float* __restrict__ f0,
                           const float* __restrict__ Hb) {
    __shared__ float sE[KK];
    __shared__ float sC[KK];
    const int b = blockIdx.x;
    const int part = blockIdx.y;
    const int t = threadIdx.x;

    {
        float acc = f0[t];
        #pragma unroll
        for (int n = 0; n < NBASIS; n++)
            acc = fmaf(Hb[t * NBASIS + n], w[b * NBASIS + n], acc);
        sE[t] = E[t];
        sC[t] = acc;
    }
    __syncthreads();

    if (part == 16) {
        for (int k = t; k < NSEG; k += blockDim.x) {
            float hi; float2 ab;
            if (k == 0) {
                hi = sE[0];            ab = make_float2(0.0f, sC[0]);
            } else if (k == KK) {
                hi = FLT_MAX;          ab = make_float2(0.0f, sC[KK - 1]);
            } else {
                float a = (sC[k] - sC[k - 1]) / (sE[k] - sE[k - 1]);
                hi = sE[k];            ab = make_float2(a, fmaf(-a, sE[k - 1], sC[k - 1]));
            }
            gSegHi[b * NSEG + k] = hi;
            gSegAB[b * NSEG + k] = ab;
        }
    }

    const int g = part * 256 + t;
    if (g < NBINS) {
        // RN bin boundaries (exact: odd * 2^-13)
        float left  = (float)(2 * g - 1) * (1.0f / 8192.0f);
        float right = (float)(2 * g + 1) * (1.0f / 8192.0f);
        int lo = 0, hi = KK;
        while (lo < hi) {                // k0 = #E <= left
            int mid = (lo + hi) >> 1;
            if (sE[mid] <= left) lo = mid + 1; else hi = mid;
        }
        int k0 = lo;
        float upper = (k0 < KK) ? sE[k0] : FLT_MAX;
        uint32_t u;
        if (upper >= right) {
            // entire bin inside extended segment k0: center value + per-bin delta
            float yc, dy;
            if (k0 == 0) {
                yc = sC[0];            dy = 0.0f;
            } else if (k0 == KK) {
                yc = sC[KK - 1];       dy = 0.0f;
            } else {
                float a = (sC[k0] - sC[k0 - 1]) / (sE[k0] - sE[k0 - 1]);
                float bint = fmaf(-a, sE[k0 - 1], sC[k0 - 1]);
                float xc = (float)g * (1.0f / 4096.0f);        // exact
                yc = fmaf(a, xc, bint);
                dy = a * (1.0f / 4096.0f);
            }
            uint16_t hc = __half_as_ushort(__float2half_rn(yc));
            uint16_t hd = __half_as_ushort(__float2half_rn(dy));
            u = ((uint32_t)hd << 16) | hc;          // finite halfs: never NaN-pattern
        } else {
            u = 0x7C000000u | (0x7C00u | (uint32_t)(k0 + 1));  // NaN sentinel + payload
        }
        gBinsU[b * NBINS_PAD + g] = u;
    } else if (part == 16 && g < NBINS_PAD) {
        gBinsU[b * NBINS_PAD + g] = 0;   // padding
    }
}

// ---------------------------------------------------------------------------
// Fast path: magic-RN index (no CVT), LDS.32, paired F2F extraction
// (__half22float2: no LOP/SHF), center+delta lerp. Kinked bins carry an fp16
// NaN center -> y is NaN -> single FSETP on y routes to the exact fp32
// segment walk (R11's minimal form).
// ---------------------------------------------------------------------------
__device__ __forceinline__ float tmo_eval(float x, const uint32_t* sBins,
                                          const float* sHi, const float2* sAB) {
    float s = fmaf(x, 4096.0f, MAGIC);          // RN -> integer g in mantissa
    int g = __float_as_int(s) & 0x1FFF;         // g in [0, 4096]
    float gf = s - MAGIC;                       // exact (Sterbenz)
    float frac = fmaf(x, 4096.0f, -gf);         // exact, in [-0.5, 0.5]
    uint32_t u = sBins[g];
    float2 f = __half22float2(*reinterpret_cast<const __half2*>(&u));  // (yc, dy)
    float y = fmaf(f.y, frac, f.x);
    if (!(y == y)) {                            // NaN => kinked bin
        int k = (int)(u & 0x3FFu) - 1;
        while (x >= sHi[k]) k++;
        float2 ab = sAB[k];
        y = fmaf(ab.x, x, ab.y);
    }
    return __saturatef(y);
}

// ---------------------------------------------------------------------------
// Main kernel: grid (148, 8) = 1184 blocks = one uniform wave at 8 CTAs/SM
// (~19.5 KB smem, 32-reg cap). Software pipeline: next LDG.128 in flight.
// ---------------------------------------------------------------------------
__global__ void __launch_bounds__(256, 8)
tmo_apply(const float* __restrict__ img, float* __restrict__ out) {
    __shared__ uint32_t sBins[NBINS_PAD];   // 16.0 KB
    __shared__ float    sHi[NSEG];          // ~1 KB
    __shared__ float2   sAB[NSEG];          // ~2 KB

    const int b = blockIdx.y;

    {
        const uint4* src = reinterpret_cast<const uint4*>(gBinsU + (size_t)b * NBINS_PAD);
        uint4* dst = reinterpret_cast<uint4*>(sBins);
        for (int i = threadIdx.x; i < NBINS_PAD / 4; i += blockDim.x) dst[i] = src[i];
        for (int i = threadIdx.x; i < NSEG; i += blockDim.x) {
            sHi[i] = gSegHi[b * NSEG + i];
            sAB[i] = gSegAB[b * NSEG + i];
        }
    }
    __syncthreads();

    const float4* in4  = reinterpret_cast<const float4*>(img + (size_t)b * PIX_PER_BATCH);
    float4*       out4 = reinterpret_cast<float4*>(out + (size_t)b * PIX_PER_BATCH);

    int i = blockIdx.x * blockDim.x + threadIdx.x;   // < STRIDE <= NF4, so >=1 elem

    float4 v = in4[i];
    int nxt = i + STRIDE;

    #pragma unroll 1
    while (nxt < NF4) {
        float4 vn = in4[nxt];            // prefetch: overlaps with processing below
        float4 r;
        r.x = tmo_eval(v.x, sBins, sHi, sAB);
        r.y = tmo_eval(v.y, sBins, sHi, sAB);
        r.z = tmo_eval(v.z, sBins, sHi, sAB);
        r.w = tmo_eval(v.w, sBins, sHi, sAB);
        out4[i] = r;
        v = vn;
        i = nxt;
        nxt += STRIDE;
    }
    {
        float4 r;
        r.x = tmo_eval(v.x, sBins, sHi, sAB);
        r.y = tmo_eval(v.y, sBins, sHi, sAB);
        r.z = tmo_eval(v.z, sBins, sHi, sAB);
        r.w = tmo_eval(v.w, sBins, sHi, sAB);
        out4[i] = r;
    }
}

extern "C" void kernel_launch(void* const* d_in, const int* in_sizes, int n_in,
                              void* d_out, int out_size) {
    const float* hdr = (const float*)d_in[0];   // [B,C,H,W]
    const float* w   = (const float*)d_in[1];   // [B,NB]
    const float* E   = (const float*)d_in[2];   // [K]
    const float* f0  = (const float*)d_in[3];   // [K]
    const float* Hb  = (const float*)d_in[4];   // [K,NB]
    float* out = (float*)d_out;

    tmo_tables<<<dim3(BB, 17), 256>>>(w, E, f0, Hb);

    dim3 grid(GX, BB);   // 1184 blocks = single uniform wave at 8 CTAs/SM
    tmo_apply<<<grid, 256>>>(hdr, out);
}